// round 8
// baseline (speedup 1.0000x reference)
#include <cuda_runtime.h>
#include <cuda_bf16.h>
#include <cstdint>
#include <cstddef>

// ============================================================================
// SkilledLoRALinear (GB300 / sm_103a) — legacy-tensor-core path.
// tcgen05 is unavailable (harness PTX targets compute_103, no 'a' feature),
// so the GEMM uses mma.sync.m16n8k16 bf16 with a 3-pass hi/lo split.
//
//   out[b] = input[b] @ (W + (1/R)·(wA[b] @ wB[b])^T)^T + bias
//
// k0 convert_inp  : input fp32 -> bf16 hi/lo global arrays
// k1 routing      : logits -> per-sample wA (IN x R), wB (R x OUT)
// k2 weff         : W_eff[b] = W + (1/16)·(wA@wB)^T -> bf16 hi/lo
// k3 gemm         : batched 128x128-tile GEMM, cp.async 3-stage pipeline,
//                   ldmatrix + mma.sync bf16, fp32 accum, 3 passes (hh,lh,hl)
// ============================================================================

#define DEVINL __device__ __forceinline__

static constexpr int BN   = 16;
static constexpr int SN   = 4096;
static constexpr int INF  = 1024;
static constexpr int OUTF = 1024;
static constexpr int RNK  = 16;
static constexpr int NSK  = 16;

// ---- device-global scratch (allocation-free contract) ----
__device__ float g_wA[BN * INF * RNK];
__device__ float g_wB[BN * RNK * OUTF];
__device__ __nv_bfloat16 g_Ahi[(size_t)BN * SN * INF];   // 128 MB
__device__ __nv_bfloat16 g_Alo[(size_t)BN * SN * INF];   // 128 MB
__device__ __nv_bfloat16 g_Bhi[(size_t)BN * OUTF * INF]; // 32 MB
__device__ __nv_bfloat16 g_Blo[(size_t)BN * OUTF * INF]; // 32 MB

// ============================================================================
// helpers
// ============================================================================
DEVINL uint32_t smem_u32(const void* p) {
    uint32_t a;
    asm("{ .reg .u64 t; cvta.to.shared.u64 t, %1; cvt.u32.u64 %0, t; }"
        : "=r"(a) : "l"(p));
    return a;
}
DEVINL void cp16(uint32_t sdst, const void* gsrc) {
    asm volatile("cp.async.cg.shared.global [%0], [%1], 16;"
                 :: "r"(sdst), "l"(__cvta_generic_to_global(gsrc)) : "memory");
}
#define CP_COMMIT() asm volatile("cp.async.commit_group;" ::: "memory")
#define CP_WAIT(n)  asm volatile("cp.async.wait_group %0;" :: "n"(n) : "memory")

DEVINL void ldsm_x4(uint32_t& r0, uint32_t& r1, uint32_t& r2, uint32_t& r3,
                    uint32_t addr) {
    asm volatile("ldmatrix.sync.aligned.m8n8.x4.shared.b16 {%0,%1,%2,%3}, [%4];"
                 : "=r"(r0), "=r"(r1), "=r"(r2), "=r"(r3) : "r"(addr));
}
DEVINL void mma_bf16(float* c, const uint32_t* a, const uint32_t* b) {
    asm volatile(
        "mma.sync.aligned.m16n8k16.row.col.f32.bf16.bf16.f32 "
        "{%0,%1,%2,%3}, {%4,%5,%6,%7}, {%8,%9}, {%0,%1,%2,%3};"
        : "+f"(c[0]), "+f"(c[1]), "+f"(c[2]), "+f"(c[3])
        : "r"(a[0]), "r"(a[1]), "r"(a[2]), "r"(a[3]), "r"(b[0]), "r"(b[1]));
}

DEVINL uint32_t pack2(__nv_bfloat16 a, __nv_bfloat16 b) {
    uint16_t ua = *reinterpret_cast<uint16_t*>(&a);
    uint16_t ub = *reinterpret_cast<uint16_t*>(&b);
    return (uint32_t)ua | ((uint32_t)ub << 16);
}

// ============================================================================
// k0: input fp32 -> bf16 hi/lo
// ============================================================================
__global__ void convert_inp(const float* __restrict__ inp) {
    size_t gid = (size_t)blockIdx.x * blockDim.x + threadIdx.x;  // 16M threads
    size_t i = gid * 4;
    float4 v = *reinterpret_cast<const float4*>(inp + i);
    __nv_bfloat16 h0 = __float2bfloat16_rn(v.x), h1 = __float2bfloat16_rn(v.y);
    __nv_bfloat16 h2 = __float2bfloat16_rn(v.z), h3 = __float2bfloat16_rn(v.w);
    __nv_bfloat16 l0 = __float2bfloat16_rn(v.x - __bfloat162float(h0));
    __nv_bfloat16 l1 = __float2bfloat16_rn(v.y - __bfloat162float(h1));
    __nv_bfloat16 l2 = __float2bfloat16_rn(v.z - __bfloat162float(h2));
    __nv_bfloat16 l3 = __float2bfloat16_rn(v.w - __bfloat162float(h3));
    uint2 hp = make_uint2(pack2(h0, h1), pack2(h2, h3));
    uint2 lp = make_uint2(pack2(l0, l1), pack2(l2, l3));
    reinterpret_cast<uint2*>(g_Ahi)[gid] = hp;
    reinterpret_cast<uint2*>(g_Alo)[gid] = lp;
}

// ============================================================================
// k1: routing -> wA, wB
// ============================================================================
__global__ void routing_kernel(const float* __restrict__ slog,
                               const float* __restrict__ sA,
                               const float* __restrict__ sB,
                               const int* __restrict__ tids) {
    int b = blockIdx.x;
    __shared__ float sg[NSK];
    int tid = threadIdx.x;
    if (tid < NSK) {
        float x = slog[tids[b] * NSK + tid];
        sg[tid] = 1.0f / (1.0f + expf(-x));
    }
    __syncthreads();
    float w[NSK]; float ssum = 0.0f;
#pragma unroll
    for (int s = 0; s < NSK; s++) { w[s] = sg[s]; ssum += w[s]; }
    float inv = 1.0f / (ssum + 1e-12f);
#pragma unroll
    for (int s = 0; s < NSK; s++) w[s] *= inv;

    const int NCOL = INF * RNK;  // 16384 == RNK*OUTF
    for (int c = tid; c < NCOL; c += blockDim.x) {
        float a = 0.0f, bb = 0.0f;
#pragma unroll
        for (int s = 0; s < NSK; s++) {
            a  += w[s] * sA[s * NCOL + c];
            bb += w[s] * sB[s * NCOL + c];
        }
        g_wA[b * NCOL + c] = a;
        g_wB[b * NCOL + c] = bb;
    }
}

// ============================================================================
// k2: W_eff -> bf16 hi/lo
// ============================================================================
__global__ void weff_kernel(const float* __restrict__ w) {
    __shared__ float sA[64][17];
    __shared__ float sB[16][64];
    int b  = blockIdx.z;
    int i0 = blockIdx.x * 64, o0 = blockIdx.y * 64;
    int tid = threadIdx.x;
    for (int t = tid; t < 1024; t += 256) {
        int ii = t >> 4, r = t & 15;
        sA[ii][r] = g_wA[b * 16384 + (i0 + ii) * RNK + r];
        int rr = t >> 6, oo = t & 63;
        sB[rr][oo] = g_wB[b * 16384 + rr * OUTF + o0 + oo];
    }
    __syncthreads();
    int to = (tid >> 4) * 4, ti = (tid & 15) * 4;
    float acc[4][4] = {};
#pragma unroll
    for (int r = 0; r < RNK; r++) {
        float av[4], bv[4];
#pragma unroll
        for (int x = 0; x < 4; x++) av[x] = sA[ti + x][r];
#pragma unroll
        for (int x = 0; x < 4; x++) bv[x] = sB[r][to + x];
#pragma unroll
        for (int oi = 0; oi < 4; oi++)
#pragma unroll
            for (int ii = 0; ii < 4; ii++)
                acc[oi][ii] += bv[oi] * av[ii];
    }
#pragma unroll
    for (int oi = 0; oi < 4; oi++) {
        size_t row = (size_t)(o0 + to + oi) * INF + i0 + ti;
        float4 wv = *reinterpret_cast<const float4*>(w + row);
        float o[4];
        o[0] = wv.x + 0.0625f * acc[oi][0];
        o[1] = wv.y + 0.0625f * acc[oi][1];
        o[2] = wv.z + 0.0625f * acc[oi][2];
        o[3] = wv.w + 0.0625f * acc[oi][3];
        __nv_bfloat16 h[4], l[4];
#pragma unroll
        for (int x = 0; x < 4; x++) {
            h[x] = __float2bfloat16_rn(o[x]);
            l[x] = __float2bfloat16_rn(o[x] - __bfloat162float(h[x]));
        }
        size_t idx = (size_t)b * OUTF * INF + row;
        *reinterpret_cast<uint2*>(g_Bhi + idx) = make_uint2(pack2(h[0], h[1]), pack2(h[2], h[3]));
        *reinterpret_cast<uint2*>(g_Blo + idx) = make_uint2(pack2(l[0], l[1]), pack2(l[2], l[3]));
    }
}

// ============================================================================
// k3: GEMM  out[b] = A[b] @ Weff[b]^T + bias  (both operands K-major)
// CTA tile 128x128, K_CHUNK=64, 3 cp.async stages, 8 warps @ 64x32
// ============================================================================
static constexpr int KC       = 64;                 // bf16 per chunk (128 B rows)
static constexpr int NCHUNK   = INF / KC;           // 16
static constexpr int AHI_OFF  = 0;                  // 128 x 128B = 16 KB each
static constexpr int ALO_OFF  = 16384;
static constexpr int BHI_OFF  = 32768;
static constexpr int BLO_OFF  = 49152;
static constexpr int STG      = 65536;              // 64 KB / stage
static constexpr int SMEM_GEMM = 3 * STG;           // 192 KB

DEVINL void load_stage(uint32_t sbase, int stg,
                       const __nv_bfloat16* Ah, const __nv_bfloat16* Al,
                       const __nv_bfloat16* Bh, const __nv_bfloat16* Bl,
                       int kc, int tid) {
    uint32_t base = sbase + stg * STG;
    const int kb = kc * KC;
    const int lrow = tid >> 3, lch = tid & 7;
#pragma unroll
    for (int j = 0; j < 4; j++) {
        int row = lrow + j * 32;
        uint32_t soff = row * 128 + (((uint32_t)(lch ^ (row & 7))) << 4);
        size_t goff = (size_t)row * INF + kb + lch * 8;
        cp16(base + AHI_OFF + soff, Ah + goff);
        cp16(base + ALO_OFF + soff, Al + goff);
        cp16(base + BHI_OFF + soff, Bh + goff);
        cp16(base + BLO_OFF + soff, Bl + goff);
    }
}

__global__ void __launch_bounds__(256, 1)
gemm_kernel(const float* __restrict__ bias, float* __restrict__ out) {
    extern __shared__ char smem[];
    const int tid  = threadIdx.x;
    const int lane = tid & 31, wid = tid >> 5;
    const int o0 = blockIdx.x * 128;
    const int s0 = blockIdx.y * 128;
    const int b  = blockIdx.z;
    const int wr = wid >> 2, wc = wid & 3;     // 2 x 4 warp grid

    uint32_t sb = smem_u32(smem);
    const __nv_bfloat16* Ah = g_Ahi + ((size_t)b * SN + s0) * INF;
    const __nv_bfloat16* Al = g_Alo + ((size_t)b * SN + s0) * INF;
    const __nv_bfloat16* Bh = g_Bhi + ((size_t)b * OUTF + o0) * INF;
    const __nv_bfloat16* Bl = g_Blo + ((size_t)b * OUTF + o0) * INF;

    float acc[4][4][4];
#pragma unroll
    for (int mi = 0; mi < 4; mi++)
#pragma unroll
        for (int ni = 0; ni < 4; ni++)
#pragma unroll
            for (int x = 0; x < 4; x++) acc[mi][ni][x] = 0.0f;

    // prologue: fill 3 stages
#pragma unroll
    for (int s = 0; s < 3; s++) {
        load_stage(sb, s, Ah, Al, Bh, Bl, s, tid);
        CP_COMMIT();
    }

    const int arow = lane & 15, akh = lane >> 4;
    const int bg = lane >> 3, brr = lane & 7;

    for (int k = 0; k < NCHUNK; k++) {
        CP_WAIT(2);
        __syncthreads();
        uint32_t base = sb + (k % 3) * STG;
#pragma unroll
        for (int ks = 0; ks < 4; ks++) {
            uint32_t ahf[4][4], alf[4][4];
#pragma unroll
            for (int mi = 0; mi < 4; mi++) {
                int row = wr * 64 + mi * 16 + arow;
                int ch = ks * 2 + akh;
                uint32_t ad = base + AHI_OFF + row * 128
                            + (((uint32_t)(ch ^ (row & 7))) << 4);
                ldsm_x4(ahf[mi][0], ahf[mi][1], ahf[mi][2], ahf[mi][3], ad);
                ldsm_x4(alf[mi][0], alf[mi][1], alf[mi][2], alf[mi][3],
                        ad + (ALO_OFF - AHI_OFF));
            }
            // B fragments: NON-trans ldmatrix. smem tile is [n][k] with k
            // contiguous, so lane l <- stored[l/4][(l%4)*2+c] is exactly the
            // mma.m16n8k16 col-major B fragment (k=(l%4)*2+c, n=l/4).
            uint32_t bhf[4][2], blf[4][2];
#pragma unroll
            for (int np = 0; np < 2; np++) {
                int row = wc * 32 + np * 16 + ((bg >> 1) << 3) + brr;
                int ch = ks * 2 + (bg & 1);
                uint32_t bd = base + BHI_OFF + row * 128
                            + (((uint32_t)(ch ^ (row & 7))) << 4);
                ldsm_x4(bhf[2 * np][0], bhf[2 * np][1],
                        bhf[2 * np + 1][0], bhf[2 * np + 1][1], bd);
                ldsm_x4(blf[2 * np][0], blf[2 * np][1],
                        blf[2 * np + 1][0], blf[2 * np + 1][1],
                        bd + (BLO_OFF - BHI_OFF));
            }
#pragma unroll
            for (int mi = 0; mi < 4; mi++)
#pragma unroll
                for (int ni = 0; ni < 4; ni++) {
                    mma_bf16(acc[mi][ni], ahf[mi], bhf[ni]);
                    mma_bf16(acc[mi][ni], alf[mi], bhf[ni]);
                    mma_bf16(acc[mi][ni], ahf[mi], blf[ni]);
                }
        }
        __syncthreads();
        if (k + 3 < NCHUNK)
            load_stage(sb, (k + 3) % 3, Ah, Al, Bh, Bl, k + 3, tid);
        CP_COMMIT();
    }

    // epilogue: direct global stores with bias
#pragma unroll
    for (int mi = 0; mi < 4; mi++) {
#pragma unroll
        for (int ni = 0; ni < 4; ni++) {
            int row = s0 + wr * 64 + mi * 16 + (lane >> 2);
            int col = o0 + wc * 32 + ni * 8 + (lane & 3) * 2;
            float2 bv = *reinterpret_cast<const float2*>(bias + col);
            size_t off = ((size_t)b * SN + row) * OUTF + col;
            float2 v0 = make_float2(acc[mi][ni][0] + bv.x, acc[mi][ni][1] + bv.y);
            float2 v1 = make_float2(acc[mi][ni][2] + bv.x, acc[mi][ni][3] + bv.y);
            *reinterpret_cast<float2*>(out + off) = v0;
            *reinterpret_cast<float2*>(out + off + (size_t)8 * OUTF) = v1;
        }
    }
}

// ============================================================================
// launch
// ============================================================================
extern "C" void kernel_launch(void* const* d_in, const int* in_sizes, int n_in,
                              void* d_out, int out_size) {
    const float* inp  = (const float*)d_in[0];
    const float* slog = (const float*)d_in[1];
    const float* w    = (const float*)d_in[2];
    const float* bias = (const float*)d_in[3];
    const float* sA   = (const float*)d_in[4];
    const float* sB   = (const float*)d_in[5];
    const int*   tids = (const int*)d_in[6];
    float* out = (float*)d_out;

    convert_inp<<<65536, 256>>>(inp);                       // 64M elems / 4 per thread
    routing_kernel<<<BN, 256>>>(slog, sA, sB, tids);
    weff_kernel<<<dim3(INF / 64, OUTF / 64, BN), 256>>>(w);

    cudaFuncSetAttribute(gemm_kernel, cudaFuncAttributeMaxDynamicSharedMemorySize,
                         SMEM_GEMM);
    gemm_kernel<<<dim3(OUTF / 128, SN / 128, BN), 256, SMEM_GEMM>>>(bias, out);
}

// round 9
// speedup vs baseline: 1.1617x; 1.1617x over previous
#include <cuda_runtime.h>
#include <cuda_fp16.h>
#include <cstdint>
#include <cstddef>

// ============================================================================
// SkilledLoRALinear (GB300 / sm_103a) — legacy mma.sync path (tcgen05 not
// available at compute_103).
//
//   out[b] = input[b] @ (W + (1/R)·(wA[b] @ wB[b])^T)^T + bias
//
// R8 profile: tensor=74.4% (tensor-bound), overhead kernels 339us.
// This round: 2-pass fp16 split (was 3-pass bf16; err budget 2.8e-4 << 1e-3)
// and convert_inp fused into the GEMM (fp32 A loaded by cp.async, converted
// to fp16 hi/lo smem tiles overlapped with MMA of previous chunk).
//
// k1 routing : logits -> per-sample wA (IN x R), wB (R x OUT)   [64 CTAs]
// k2 weff    : W_eff[b] = W + (1/16)·(wA@wB)^T -> fp16
// k3 gemm    : batched 128x128 tile, K_CHUNK=64, 3-stage cp.async,
//              in-loop fp32->fp16 hi/lo convert (double-buffered),
//              ldmatrix + mma.sync.m16n8k16.f16, fp32 accum, 2 passes.
// ============================================================================

#define DEVINL __device__ __forceinline__

static constexpr int BN   = 16;
static constexpr int SN   = 4096;
static constexpr int INF  = 1024;
static constexpr int OUTF = 1024;
static constexpr int RNK  = 16;
static constexpr int NSK  = 16;

// ---- device-global scratch ----
__device__ float g_wA[BN * INF * RNK];
__device__ float g_wB[BN * RNK * OUTF];
__device__ __half g_Bh[(size_t)BN * OUTF * INF];   // W_eff fp16, 32 MB

// ============================================================================
// helpers
// ============================================================================
DEVINL uint32_t smem_u32(const void* p) {
    uint32_t a;
    asm("{ .reg .u64 t; cvta.to.shared.u64 t, %1; cvt.u32.u64 %0, t; }"
        : "=r"(a) : "l"(p));
    return a;
}
DEVINL void cp16(uint32_t sdst, const void* gsrc) {
    asm volatile("cp.async.cg.shared.global [%0], [%1], 16;"
                 :: "r"(sdst), "l"(__cvta_generic_to_global(gsrc)) : "memory");
}
#define CP_COMMIT() asm volatile("cp.async.commit_group;" ::: "memory")
#define CP_WAIT(n)  asm volatile("cp.async.wait_group %0;" :: "n"(n) : "memory")

DEVINL void ldsm_x4(uint32_t& r0, uint32_t& r1, uint32_t& r2, uint32_t& r3,
                    uint32_t addr) {
    asm volatile("ldmatrix.sync.aligned.m8n8.x4.shared.b16 {%0,%1,%2,%3}, [%4];"
                 : "=r"(r0), "=r"(r1), "=r"(r2), "=r"(r3) : "r"(addr));
}
DEVINL void mma_f16(float* c, const uint32_t* a, const uint32_t* b) {
    asm volatile(
        "mma.sync.aligned.m16n8k16.row.col.f32.f16.f16.f32 "
        "{%0,%1,%2,%3}, {%4,%5,%6,%7}, {%8,%9}, {%0,%1,%2,%3};"
        : "+f"(c[0]), "+f"(c[1]), "+f"(c[2]), "+f"(c[3])
        : "r"(a[0]), "r"(a[1]), "r"(a[2]), "r"(a[3]), "r"(b[0]), "r"(b[1]));
}
DEVINL uint32_t pack2h(__half a, __half b) {
    uint16_t ua = *reinterpret_cast<uint16_t*>(&a);
    uint16_t ub = *reinterpret_cast<uint16_t*>(&b);
    return (uint32_t)ua | ((uint32_t)ub << 16);
}

// ============================================================================
// k1: routing -> wA, wB   (grid: BN x 4 for DRAM parallelism)
// ============================================================================
__global__ void routing_kernel(const float* __restrict__ slog,
                               const float* __restrict__ sA,
                               const float* __restrict__ sB,
                               const int* __restrict__ tids) {
    int b = blockIdx.x;
    int q = blockIdx.y;            // quarter of the column range
    __shared__ float sg[NSK];
    int tid = threadIdx.x;
    if (tid < NSK) {
        float x = slog[tids[b] * NSK + tid];
        sg[tid] = 1.0f / (1.0f + expf(-x));
    }
    __syncthreads();
    float w[NSK]; float ssum = 0.0f;
#pragma unroll
    for (int s = 0; s < NSK; s++) { w[s] = sg[s]; ssum += w[s]; }
    float inv = 1.0f / (ssum + 1e-12f);
#pragma unroll
    for (int s = 0; s < NSK; s++) w[s] *= inv;

    const int NCOL = INF * RNK;    // 16384 == RNK*OUTF
    const int Q = NCOL / 4;        // 4096
    for (int c = q * Q + tid; c < (q + 1) * Q; c += blockDim.x) {
        float a = 0.0f, bb = 0.0f;
#pragma unroll
        for (int s = 0; s < NSK; s++) {
            a  += w[s] * sA[s * NCOL + c];
            bb += w[s] * sB[s * NCOL + c];
        }
        g_wA[b * NCOL + c] = a;
        g_wB[b * NCOL + c] = bb;
    }
}

// ============================================================================
// k2: W_eff -> fp16
// ============================================================================
__global__ void weff_kernel(const float* __restrict__ w) {
    __shared__ float sA[64][17];
    __shared__ float sB[16][64];
    int b  = blockIdx.z;
    int i0 = blockIdx.x * 64, o0 = blockIdx.y * 64;
    int tid = threadIdx.x;
    for (int t = tid; t < 1024; t += 256) {
        int ii = t >> 4, r = t & 15;
        sA[ii][r] = g_wA[b * 16384 + (i0 + ii) * RNK + r];
        int rr = t >> 6, oo = t & 63;
        sB[rr][oo] = g_wB[b * 16384 + rr * OUTF + o0 + oo];
    }
    __syncthreads();
    int to = (tid >> 4) * 4, ti = (tid & 15) * 4;
    float acc[4][4] = {};
#pragma unroll
    for (int r = 0; r < RNK; r++) {
        float av[4], bv[4];
#pragma unroll
        for (int x = 0; x < 4; x++) av[x] = sA[ti + x][r];
#pragma unroll
        for (int x = 0; x < 4; x++) bv[x] = sB[r][to + x];
#pragma unroll
        for (int oi = 0; oi < 4; oi++)
#pragma unroll
            for (int ii = 0; ii < 4; ii++)
                acc[oi][ii] += bv[oi] * av[ii];
    }
#pragma unroll
    for (int oi = 0; oi < 4; oi++) {
        size_t row = (size_t)(o0 + to + oi) * INF + i0 + ti;
        float4 wv = *reinterpret_cast<const float4*>(w + row);
        __half h0 = __float2half_rn(wv.x + 0.0625f * acc[oi][0]);
        __half h1 = __float2half_rn(wv.y + 0.0625f * acc[oi][1]);
        __half h2 = __float2half_rn(wv.z + 0.0625f * acc[oi][2]);
        __half h3 = __float2half_rn(wv.w + 0.0625f * acc[oi][3]);
        *reinterpret_cast<uint2*>(g_Bh + (size_t)b * OUTF * INF + row) =
            make_uint2(pack2h(h0, h1), pack2h(h2, h3));
    }
}

// ============================================================================
// k3: GEMM  out[b] = A[b] @ Weff[b]^T + bias
// A loaded as fp32 (cp.async), converted in-loop to fp16 hi/lo tiles.
// ============================================================================
static constexpr int KC     = 64;                  // K per chunk
static constexpr int NCHUNK = INF / KC;            // 16
// per-stage: A fp32 128x64 (32 KB, linear 256B rows) + B fp16 128x64 (16 KB, swizzled)
static constexpr int B_OFF    = 32768;
static constexpr int STG      = 49152;             // 48 KB
static constexpr int CONV_OFF = 3 * STG;           // 147456
// conv buffer: Ah (16 KB) + Al (16 KB), double-buffered
static constexpr int CONV_BUF = 32768;
static constexpr int SMEM_GEMM = CONV_OFF + 2 * CONV_BUF;   // 212992 (208 KB)

DEVINL void load_stage(uint32_t sbase, int stg,
                       const float* __restrict__ A32,
                       const __half* __restrict__ Bh,
                       int kc, int tid) {
    uint32_t base = sbase + stg * STG;
    const int kb = kc * KC;
    // A: 128 rows x 64 fp32, linear; 2048 16B tasks
#pragma unroll
    for (int j = 0; j < 8; j++) {
        int idx = tid + j * 256;
        int row = idx >> 4, c = idx & 15;
        cp16(base + row * 256 + c * 16, A32 + (size_t)row * INF + kb + c * 4);
    }
    // B: 128 rows x 64 fp16, swizzled 128B rows; 1024 16B tasks
#pragma unroll
    for (int j = 0; j < 4; j++) {
        int idx = tid + j * 256;
        int row = idx >> 3, ch = idx & 7;
        cp16(base + B_OFF + row * 128 + (((uint32_t)(ch ^ (row & 7))) << 4),
             Bh + (size_t)row * INF + kb + ch * 8);
    }
}

// convert stage's fp32 A tile -> fp16 hi/lo tiles (swizzled, ldmatrix layout)
DEVINL void convert_tile(char* smem, int stg, uint32_t cbuf_off, int tid) {
    const char* src = smem + stg * STG;
    char* dh = smem + cbuf_off;
    char* dl = smem + cbuf_off + 16384;
#pragma unroll
    for (int j = 0; j < 8; j++) {
        int idx = tid + j * 256;            // 0..2047, 4 fp32 each
        int row = idx >> 4, c4 = idx & 15;  // k0 = c4*4
        float4 v = *reinterpret_cast<const float4*>(src + row * 256 + c4 * 16);
        __half h0 = __float2half_rn(v.x), h1 = __float2half_rn(v.y);
        __half h2 = __float2half_rn(v.z), h3 = __float2half_rn(v.w);
        __half l0 = __float2half_rn(v.x - __half2float(h0));
        __half l1 = __float2half_rn(v.y - __half2float(h1));
        __half l2 = __float2half_rn(v.z - __half2float(h2));
        __half l3 = __float2half_rn(v.w - __half2float(h3));
        int ch = c4 >> 1, sub = (c4 & 1) * 8;
        uint32_t soff = row * 128 + (((uint32_t)(ch ^ (row & 7))) << 4) + sub;
        *reinterpret_cast<uint2*>(dh + soff) = make_uint2(pack2h(h0, h1), pack2h(h2, h3));
        *reinterpret_cast<uint2*>(dl + soff) = make_uint2(pack2h(l0, l1), pack2h(l2, l3));
    }
}

__global__ void __launch_bounds__(256, 1)
gemm_kernel(const float* __restrict__ inp, const float* __restrict__ bias,
            float* __restrict__ out) {
    extern __shared__ char smem[];
    const int tid  = threadIdx.x;
    const int lane = tid & 31, wid = tid >> 5;
    const int o0 = blockIdx.x * 128;
    const int s0 = blockIdx.y * 128;
    const int b  = blockIdx.z;
    const int wr = wid >> 2, wc = wid & 3;     // 2 x 4 warp grid

    uint32_t sb = smem_u32(smem);
    const float*  A32 = inp + ((size_t)b * SN + s0) * INF;
    const __half* Bh  = g_Bh + ((size_t)b * OUTF + o0) * INF;

    float acc[4][4][4];
#pragma unroll
    for (int mi = 0; mi < 4; mi++)
#pragma unroll
        for (int ni = 0; ni < 4; ni++)
#pragma unroll
            for (int x = 0; x < 4; x++) acc[mi][ni][x] = 0.0f;

    // prologue: 3 stages in flight, convert chunk 0
#pragma unroll
    for (int s = 0; s < 3; s++) {
        load_stage(sb, s, A32, Bh, s, tid);
        CP_COMMIT();
    }
    CP_WAIT(2);
    __syncthreads();
    convert_tile(smem, 0, CONV_OFF, tid);
    int cb = 0;

    const int arow = lane & 15, akh = lane >> 4;
    const int bg = lane >> 3, brr = lane & 7;

    for (int k = 0; k < NCHUNK; k++) {
        CP_WAIT(1);              // chunk k B + chunk k+1 A32 resident
        __syncthreads();         // (also publishes convert of chunk k)

        // convert chunk k+1 into the other buffer (overlaps with MMA below)
        if (k + 1 < NCHUNK)
            convert_tile(smem, (k + 1) % 3, CONV_OFF + (cb ^ 1) * CONV_BUF, tid);

        uint32_t abase = sb + CONV_OFF + cb * CONV_BUF;
        uint32_t bbase = sb + (k % 3) * STG + B_OFF;
#pragma unroll
        for (int ks = 0; ks < 4; ks++) {
            uint32_t ahf[4][4], alf[4][4];
#pragma unroll
            for (int mi = 0; mi < 4; mi++) {
                int row = wr * 64 + mi * 16 + arow;
                int ch = ks * 2 + akh;
                uint32_t ad = abase + row * 128
                            + (((uint32_t)(ch ^ (row & 7))) << 4);
                ldsm_x4(ahf[mi][0], ahf[mi][1], ahf[mi][2], ahf[mi][3], ad);
                ldsm_x4(alf[mi][0], alf[mi][1], alf[mi][2], alf[mi][3], ad + 16384);
            }
            uint32_t bhf[4][2];
#pragma unroll
            for (int np = 0; np < 2; np++) {
                int row = wc * 32 + np * 16 + ((bg >> 1) << 3) + brr;
                int ch = ks * 2 + (bg & 1);
                uint32_t bd = bbase + row * 128
                            + (((uint32_t)(ch ^ (row & 7))) << 4);
                ldsm_x4(bhf[2 * np][0], bhf[2 * np][1],
                        bhf[2 * np + 1][0], bhf[2 * np + 1][1], bd);
            }
#pragma unroll
            for (int mi = 0; mi < 4; mi++)
#pragma unroll
                for (int ni = 0; ni < 4; ni++) {
                    mma_f16(acc[mi][ni], ahf[mi], bhf[ni]);
                    mma_f16(acc[mi][ni], alf[mi], bhf[ni]);
                }
        }
        __syncthreads();         // stage k%3 free; conv buf (cb^1) published
        if (k + 3 < NCHUNK)
            load_stage(sb, (k + 3) % 3, A32, Bh, k + 3, tid);
        CP_COMMIT();
        cb ^= 1;
    }

    // epilogue: direct global stores with bias
#pragma unroll
    for (int mi = 0; mi < 4; mi++) {
#pragma unroll
        for (int ni = 0; ni < 4; ni++) {
            int row = s0 + wr * 64 + mi * 16 + (lane >> 2);
            int col = o0 + wc * 32 + ni * 8 + (lane & 3) * 2;
            float2 bv = *reinterpret_cast<const float2*>(bias + col);
            size_t off = ((size_t)b * SN + row) * OUTF + col;
            float2 v0 = make_float2(acc[mi][ni][0] + bv.x, acc[mi][ni][1] + bv.y);
            float2 v1 = make_float2(acc[mi][ni][2] + bv.x, acc[mi][ni][3] + bv.y);
            *reinterpret_cast<float2*>(out + off) = v0;
            *reinterpret_cast<float2*>(out + off + (size_t)8 * OUTF) = v1;
        }
    }
}

// ============================================================================
// launch
// ============================================================================
extern "C" void kernel_launch(void* const* d_in, const int* in_sizes, int n_in,
                              void* d_out, int out_size) {
    const float* inp  = (const float*)d_in[0];
    const float* slog = (const float*)d_in[1];
    const float* w    = (const float*)d_in[2];
    const float* bias = (const float*)d_in[3];
    const float* sA   = (const float*)d_in[4];
    const float* sB   = (const float*)d_in[5];
    const int*   tids = (const int*)d_in[6];
    float* out = (float*)d_out;

    routing_kernel<<<dim3(BN, 4), 256>>>(slog, sA, sB, tids);
    weff_kernel<<<dim3(INF / 64, OUTF / 64, BN), 256>>>(w);

    cudaFuncSetAttribute(gemm_kernel, cudaFuncAttributeMaxDynamicSharedMemorySize,
                         SMEM_GEMM);
    gemm_kernel<<<dim3(OUTF / 128, SN / 128, BN), 256, SMEM_GEMM>>>(inp, bias, out);
}